// round 13
// baseline (speedup 1.0000x reference)
#include <cuda_runtime.h>
#include <cstdint>

#define HH 512
#define WW 512
#define CCH 3
#define SS 2
#define AA 3
#define NB 8
#define BB 2
#define SKS 9
#define AKS 7

__device__ float g_conv[CCH * SS * HH * WW];   // sigma-blurred maps

// ---------------------------------------------------------------------------
// Fused sigma blur: clip + separable 9-tap (both sigmas) per 32x32 tile.
// 1D weights (= row sums of the 2D kernel, exact rank-1) derived per CTA.
// ---------------------------------------------------------------------------
#define STW 32
#define STH 32
#define SIN 40

__global__ __launch_bounds__(256) void k_sigma(const float* __restrict__ im,
                                               const float* __restrict__ sig2d) {
    __shared__ float s_in[SIN][SIN];
    __shared__ float s_ht[SS][SIN][STW + 1];
    __shared__ float wsig[SS * 5];
    int tid = threadIdx.x;
    int c = blockIdx.z;
    int gy0 = blockIdx.y * STH, gx0 = blockIdx.x * STW;

    if (tid < SS * 5) {
        int s = tid / 5, k = tid % 5;
        float sum = 0.f;
        for (int j = 0; j < SKS; j++) sum += __ldg(&sig2d[(s * SKS + k) * SKS + j]);
        wsig[tid] = sum;
    }
    for (int i = tid; i < SIN * SIN; i += 256) {
        int r = i / SIN, q = i - r * SIN;
        int gy = gy0 + r - 4, gx = gx0 + q - 4;
        float v = 0.f;
        if (gy >= 0 && gy < HH && gx >= 0 && gx < WW) {
            v = __ldg(&im[((size_t)gy * WW + gx) * CCH + c]);
            v = fminf(fmaxf(v, 0.f), 1.f);
        }
        s_in[r][q] = v;
    }
    __syncthreads();
    float w[SS][5];
#pragma unroll
    for (int s = 0; s < SS; s++)
#pragma unroll
        for (int k = 0; k < 5; k++) w[s][k] = wsig[s * 5 + k];

    for (int i = tid; i < SIN * STW; i += 256) {
        int r = i / STW, x = i - r * STW;
        const float* row = &s_in[r][x];
        float p0 = row[0] + row[8], p1 = row[1] + row[7];
        float p2 = row[2] + row[6], p3 = row[3] + row[5];
        float m = row[4];
#pragma unroll
        for (int s = 0; s < SS; s++) {
            float acc = w[s][4] * m;
            acc = fmaf(w[s][0], p0, acc);
            acc = fmaf(w[s][1], p1, acc);
            acc = fmaf(w[s][2], p2, acc);
            acc = fmaf(w[s][3], p3, acc);
            s_ht[s][r][x] = acc;
        }
    }
    __syncthreads();

    for (int i = tid; i < STH * STW; i += 256) {
        int y = i / STW, x = i - y * STW;
#pragma unroll
        for (int s = 0; s < SS; s++) {
            const float* col = &s_ht[s][y][x];
            const int L = STW + 1;
            float p0 = col[0] + col[8 * L], p1 = col[1 * L] + col[7 * L];
            float p2 = col[2 * L] + col[6 * L], p3 = col[3 * L] + col[5 * L];
            float m = col[4 * L];
            float acc = w[s][4] * m;
            acc = fmaf(w[s][0], p0, acc);
            acc = fmaf(w[s][1], p1, acc);
            acc = fmaf(w[s][2], p2, acc);
            acc = fmaf(w[s][3], p3, acc);
            g_conv[(((size_t)c * SS + s) * HH + gy0 + y) * WW + gx0 + x] = acc;
        }
    }
}

// ---------------------------------------------------------------------------
// Packed f32x2 + ex2 helpers
// ---------------------------------------------------------------------------
union F2U { float2 f; unsigned long long u; };
__device__ __forceinline__ float2 ffma2(float2 a, float2 b, float2 c) {
    F2U A, B, C, D; A.f = a; B.f = b; C.f = c;
    asm("fma.rn.f32x2 %0, %1, %2, %3;" : "=l"(D.u) : "l"(A.u), "l"(B.u), "l"(C.u));
    return D.f;
}
__device__ __forceinline__ float2 fmul2(float2 a, float2 b) {
    F2U A, B, D; A.f = a; B.f = b;
    asm("mul.rn.f32x2 %0, %1, %2;" : "=l"(D.u) : "l"(A.u), "l"(B.u));
    return D.f;
}
__device__ __forceinline__ float2 fadd2(float2 a, float2 b) {
    F2U A, B, D; A.f = a; B.f = b;
    asm("add.rn.f32x2 %0, %1, %2;" : "=l"(D.u) : "l"(A.u), "l"(B.u));
    return D.f;
}
__device__ __forceinline__ float ex2f(float x) {
    float r; asm("ex2.approx.f32 %0, %1;" : "=f"(r) : "f"(x)); return r;
}

// ---------------------------------------------------------------------------
// K2: grid z = (c,s,b). Warp w owns x in [8w, 8w+8); lane l: p = l&3
// (binpair), xi = l>>2. Software-pipelined: iteration `row` produces iso for
// row+1 into the warp-private parity slab, then consumes row from data that
// landed across the previous __syncwarp (no STS->LDS stall). Vertical:
// register scatter rings (a0,a1) + thread-private smem gather ring (a2).
// nrm folded into the exponent: nrm*exp(kf d^2) = ex2(kf2 d^2 + lb).
// ---------------------------------------------------------------------------
#define W_T 64
#define H_T 32
#define RIN 38           // H_T + 6 input rows
#define POSP 72          // padded conv row (lanes read up to 71; pad=sentinel)

struct SMemL {
    float  conv[RIN * POSP];       // 10944 B
    float2 priv[2][8][64];         // 8192 B, [row parity][warp][pos*4+p]
    float2 h2[7][256];             // 14336 B, alpha2 hconv ring
    float  wal[AA * 4];
};

__global__ __launch_bounds__(256, 3) void k_loi(const float* __restrict__ al2d,
                                                const float* __restrict__ centers,
                                                const float* __restrict__ betas,
                                                float* __restrict__ out) {
    __shared__ SMemL sm;
    int tid = threadIdx.x;
    int l = tid & 31, w = tid >> 5;
    int p = l & 3, xi = l >> 2;
    int z = blockIdx.z;
    int b = z % BB;
    int cs = z / BB;
    int c = cs / SS, s = cs % SS;
    int gy0 = blockIdx.y * H_T;
    int gx0 = blockIdx.x * W_T;
    const float* convmap = g_conv + (size_t)cs * HH * WW;

    if (tid < AA * 4) {
        int a = tid >> 2, k = tid & 3;
        float sum = 0.f;
        for (int j = 0; j < AKS; j++) sum += __ldg(&al2d[(a * AKS + k) * AKS + j]);
        sm.wal[tid] = sum;
    }
    // conv slab (halo 3; OOB/pad -> sentinel so iso == 0 exactly)
    for (int i = tid; i < RIN * POSP; i += 256) {
        int r = i / POSP, q = i - r * POSP;
        int gy = gy0 + r - 3, gx = gx0 + q - 3;
        sm.conv[i] = (q < 70 && gy >= 0 && gy < HH && gx >= 0 && gx < WW)
                     ? __ldg(&convmap[(size_t)gy * WW + gx]) : -1e30f;
    }
    float cn0 = __ldg(&centers[2 * p]);
    float cn1 = __ldg(&centers[2 * p + 1]);
    __syncthreads();

    float2 wk[AA][4];
#pragma unroll
    for (int a = 0; a < AA; a++)
#pragma unroll
        for (int k = 0; k < 4; k++) {
            float wv = sm.wal[a * 4 + k];
            wk[a][k] = make_float2(wv, wv);
        }

    const size_t ASTR = (size_t)BB * SS * CCH * HH * WW * (NB / 2);  // float2

    float invb = 1.f / __ldg(&betas[b]);
    float nrm = 0.3989422804014327f * invb;
    float kf2 = -0.5f * invb * invb * 1.44269504088896f;   // kf * log2(e)
    float lb = __log2f(nrm);

    float2 acc[2][7];
    float2* outb = (float2*)out +
                   (size_t)((b * SS + s) * CCH + c) * (HH * WW * (NB / 2));
    const int xoff = 8 * w + xi;

    // ---- prologue: produce row 0, prefetch conv for row 1 ----
    float2 cur1;                 // own iso tap (x = xoff) for current row
    {
        float cva = sm.conv[xoff];
        float cvb = sm.conv[xoff + 8];
        float da0 = cva - cn0, da1 = cva - cn1;
        float db0 = cvb - cn0, db1 = cvb - cn1;
        float2 e2;
        cur1.x = ex2f(fmaf(kf2, da0 * da0, lb));
        cur1.y = ex2f(fmaf(kf2, da1 * da1, lb));
        e2.x = ex2f(fmaf(kf2, db0 * db0, lb));
        e2.y = ex2f(fmaf(kf2, db1 * db1, lb));
        float2* ps = sm.priv[0][w];
        ps[xi * 4 + p] = cur1;
        ps[(xi + 8) * 4 + p] = e2;
    }
    float cvaN = sm.conv[POSP + xoff];
    float cvbN = sm.conv[POSP + xoff + 8];
    __syncwarp();

#pragma unroll 1
    for (int r7 = 0; r7 < 6; r7++) {
#pragma unroll
        for (int rr = 0; rr < 7; rr++) {
            int row = r7 * 7 + rr;
            if (row < RIN) {
                // ---- produce row+1 into parity (row+1)&1 ----
                float2 nxt1;
                if (row + 1 < RIN) {
                    float da0 = cvaN - cn0, da1 = cvaN - cn1;
                    float db0 = cvbN - cn0, db1 = cvbN - cn1;
                    float2 f2;
                    nxt1.x = ex2f(fmaf(kf2, da0 * da0, lb));
                    nxt1.y = ex2f(fmaf(kf2, da1 * da1, lb));
                    f2.x = ex2f(fmaf(kf2, db0 * db0, lb));
                    f2.y = ex2f(fmaf(kf2, db1 * db1, lb));
                    float2* ps = sm.priv[(row + 1) & 1][w];
                    ps[xi * 4 + p] = nxt1;
                    ps[(xi + 8) * 4 + p] = f2;
                }
                // ---- prefetch conv for row+2 ----
                if (row + 2 < RIN) {
                    cvaN = sm.conv[(row + 2) * POSP + xoff];
                    cvbN = sm.conv[(row + 2) * POSP + xoff + 8];
                }

                // ---- consume row (slab data landed across prev syncwarp) ----
                const float2* wp8 = &sm.priv[row & 1][w][xi * 4 + p];
                float2 t1 = wp8[4],  t2 = wp8[8],  t3 = wp8[12];
                float2 t4 = wp8[16], t5 = wp8[20], t6 = wp8[24];
                float2 s0 = fadd2(cur1, t6);
                float2 s1 = fadd2(t1, t5);
                float2 s2 = fadd2(t2, t4);

                float2 hv0 = fmul2(wk[0][3], t3);
                float2 hv1 = fmul2(wk[1][3], t3);
                float2 hv2 = fmul2(wk[2][3], t3);
                hv0 = ffma2(wk[0][0], s0, hv0);
                hv1 = ffma2(wk[1][0], s0, hv1);
                hv2 = ffma2(wk[2][0], s0, hv2);
                hv0 = ffma2(wk[0][1], s1, hv0);
                hv1 = ffma2(wk[1][1], s1, hv1);
                hv2 = ffma2(wk[2][1], s1, hv2);
                hv0 = ffma2(wk[0][2], s2, hv0);
                hv1 = ffma2(wk[1][2], s2, hv1);
                hv2 = ffma2(wk[2][2], s2, hv2);

                // alpha2: thread-private smem ring
                sm.h2[rr][tid] = hv2;

                // alphas 0,1: register scatter rings (stale slots are
                // re-initialized at t==0 before any store)
#pragma unroll
                for (int t = 0; t < 7; t++) {
                    const int slot = ((rr - t) % 7 + 7) % 7;
                    const int wi = (t < 4) ? t : 6 - t;
                    if (t == 0) {
                        acc[0][slot] = fmul2(wk[0][wi], hv0);
                        acc[1][slot] = fmul2(wk[1][wi], hv1);
                    } else {
                        acc[0][slot] = ffma2(wk[0][wi], hv0, acc[0][slot]);
                        acc[1][slot] = ffma2(wk[1][wi], hv1, acc[1][slot]);
                    }
                }

                // ---- completed output row y = row - 6 ----
                if (row >= 6) {
                    const int slot = (rr + 1) % 7;
                    float2 g0 = sm.h2[(rr + 1) % 7][tid];
                    float2 g1 = sm.h2[(rr + 2) % 7][tid];
                    float2 g2 = sm.h2[(rr + 3) % 7][tid];
                    float2 g3 = sm.h2[(rr + 4) % 7][tid];
                    float2 g4 = sm.h2[(rr + 5) % 7][tid];
                    float2 g5 = sm.h2[(rr + 6) % 7][tid];
                    float2 sA = fadd2(g0, hv2);
                    float2 sB = fadd2(g1, g5);
                    float2 sC = fadd2(g2, g4);
                    float2 o2 = fmul2(wk[2][3], g3);
                    o2 = ffma2(wk[2][0], sA, o2);
                    o2 = ffma2(wk[2][1], sB, o2);
                    o2 = ffma2(wk[2][2], sC, o2);

                    size_t off = ((size_t)(gy0 + row - 6) * WW + gx0 + xoff)
                                 * (NB / 2) + p;
                    outb[off] = acc[0][slot];
                    outb[off + ASTR] = acc[1][slot];
                    outb[off + 2 * ASTR] = o2;
                }

                cur1 = nxt1;
            }
            __syncwarp();
        }
    }
}

// ---------------------------------------------------------------------------
extern "C" void kernel_launch(void* const* d_in, const int* in_sizes, int n_in,
                              void* d_out, int out_size) {
    const float* im      = (const float*)d_in[0];   // (512,512,3)
    const float* sig2d   = (const float*)d_in[1];   // (2,9,9)
    const float* al2d    = (const float*)d_in[2];   // (3,7,7)
    const float* centers = (const float*)d_in[3];   // (8,)
    const float* betas   = (const float*)d_in[4];   // (2,)
    float* out = (float*)d_out;

    dim3 gs(WW / STW, HH / STH, CCH);
    k_sigma<<<gs, 256>>>(im, sig2d);
    dim3 g(WW / W_T, HH / H_T, CCH * SS * BB);
    k_loi<<<g, 256>>>(al2d, centers, betas, out);
}

// round 14
// speedup vs baseline: 1.0548x; 1.0548x over previous
#include <cuda_runtime.h>
#include <cstdint>

#define HH 512
#define WW 512
#define CCH 3
#define SS 2
#define AA 3
#define NB 8
#define BB 2
#define SKS 9
#define AKS 7

__device__ float g_conv[CCH * SS * HH * WW];   // sigma-blurred maps

// ---------------------------------------------------------------------------
// Fused sigma blur: clip + separable 9-tap (both sigmas) per 32x32 tile.
// 1D weights (= row sums of the 2D kernel, exact rank-1) derived per CTA.
// ---------------------------------------------------------------------------
#define STW 32
#define STH 32
#define SIN 40

__global__ __launch_bounds__(256) void k_sigma(const float* __restrict__ im,
                                               const float* __restrict__ sig2d) {
    __shared__ float s_in[SIN][SIN];
    __shared__ float s_ht[SS][SIN][STW + 1];
    __shared__ float wsig[SS * 5];
    int tid = threadIdx.x;
    int c = blockIdx.z;
    int gy0 = blockIdx.y * STH, gx0 = blockIdx.x * STW;

    if (tid < SS * 5) {
        int s = tid / 5, k = tid % 5;
        float sum = 0.f;
        for (int j = 0; j < SKS; j++) sum += __ldg(&sig2d[(s * SKS + k) * SKS + j]);
        wsig[tid] = sum;
    }
    for (int i = tid; i < SIN * SIN; i += 256) {
        int r = i / SIN, q = i - r * SIN;
        int gy = gy0 + r - 4, gx = gx0 + q - 4;
        float v = 0.f;
        if (gy >= 0 && gy < HH && gx >= 0 && gx < WW) {
            v = __ldg(&im[((size_t)gy * WW + gx) * CCH + c]);
            v = fminf(fmaxf(v, 0.f), 1.f);
        }
        s_in[r][q] = v;
    }
    __syncthreads();
    float w[SS][5];
#pragma unroll
    for (int s = 0; s < SS; s++)
#pragma unroll
        for (int k = 0; k < 5; k++) w[s][k] = wsig[s * 5 + k];

    for (int i = tid; i < SIN * STW; i += 256) {
        int r = i / STW, x = i - r * STW;
        const float* row = &s_in[r][x];
        float p0 = row[0] + row[8], p1 = row[1] + row[7];
        float p2 = row[2] + row[6], p3 = row[3] + row[5];
        float m = row[4];
#pragma unroll
        for (int s = 0; s < SS; s++) {
            float acc = w[s][4] * m;
            acc = fmaf(w[s][0], p0, acc);
            acc = fmaf(w[s][1], p1, acc);
            acc = fmaf(w[s][2], p2, acc);
            acc = fmaf(w[s][3], p3, acc);
            s_ht[s][r][x] = acc;
        }
    }
    __syncthreads();

    for (int i = tid; i < STH * STW; i += 256) {
        int y = i / STW, x = i - y * STW;
#pragma unroll
        for (int s = 0; s < SS; s++) {
            const float* col = &s_ht[s][y][x];
            const int L = STW + 1;
            float p0 = col[0] + col[8 * L], p1 = col[1 * L] + col[7 * L];
            float p2 = col[2 * L] + col[6 * L], p3 = col[3 * L] + col[5 * L];
            float m = col[4 * L];
            float acc = w[s][4] * m;
            acc = fmaf(w[s][0], p0, acc);
            acc = fmaf(w[s][1], p1, acc);
            acc = fmaf(w[s][2], p2, acc);
            acc = fmaf(w[s][3], p3, acc);
            g_conv[(((size_t)c * SS + s) * HH + gy0 + y) * WW + gx0 + x] = acc;
        }
    }
}

// ---------------------------------------------------------------------------
// Packed f32x2 + ex2 helpers
// ---------------------------------------------------------------------------
union F2U { float2 f; unsigned long long u; };
__device__ __forceinline__ float2 ffma2(float2 a, float2 b, float2 c) {
    F2U A, B, C, D; A.f = a; B.f = b; C.f = c;
    asm("fma.rn.f32x2 %0, %1, %2, %3;" : "=l"(D.u) : "l"(A.u), "l"(B.u), "l"(C.u));
    return D.f;
}
__device__ __forceinline__ float2 fmul2(float2 a, float2 b) {
    F2U A, B, D; A.f = a; B.f = b;
    asm("mul.rn.f32x2 %0, %1, %2;" : "=l"(D.u) : "l"(A.u), "l"(B.u));
    return D.f;
}
__device__ __forceinline__ float2 fadd2(float2 a, float2 b) {
    F2U A, B, D; A.f = a; B.f = b;
    asm("add.rn.f32x2 %0, %1, %2;" : "=l"(D.u) : "l"(A.u), "l"(B.u));
    return D.f;
}
__device__ __forceinline__ float ex2f(float x) {
    float r; asm("ex2.approx.f32 %0, %1;" : "=f"(r) : "f"(x)); return r;
}

// ---------------------------------------------------------------------------
// K2: grid z = (c,s,b). Warp w owns x in [8w, 8w+8); lane l: p = l&3
// (binpair), xi = l>>2. Per row: warp produces its 16 iso positions into a
// warp-private parity slab (one __syncwarp), consumes the 7-tap window,
// hconv for 3 alphas. Vertical: register scatter rings for alphas 0,1 AND a
// 7-deep register DELAY LINE for alpha2 (slot indices static via the rr
// unroll -> pure register rotation, no shared memory, no MOVs).
// ---------------------------------------------------------------------------
#define W_T 64
#define H_T 32
#define RIN 38           // H_T + 6 input rows
#define POSP 72          // padded conv row (lanes read up to 71; pad=sentinel)

struct SMemL {
    float  conv[RIN * POSP];       // 10944 B
    float2 priv[2][8][64];         // 8192 B, [row parity][warp][pos*4+p]
    float  wal[AA * 4];
};

__global__ __launch_bounds__(256, 3) void k_loi(const float* __restrict__ al2d,
                                                const float* __restrict__ centers,
                                                const float* __restrict__ betas,
                                                float* __restrict__ out) {
    __shared__ SMemL sm;
    int tid = threadIdx.x;
    int l = tid & 31, w = tid >> 5;
    int p = l & 3, xi = l >> 2;
    int z = blockIdx.z;
    int b = z % BB;
    int cs = z / BB;
    int c = cs / SS, s = cs % SS;
    int gy0 = blockIdx.y * H_T;
    int gx0 = blockIdx.x * W_T;
    const float* convmap = g_conv + (size_t)cs * HH * WW;

    if (tid < AA * 4) {
        int a = tid >> 2, k = tid & 3;
        float sum = 0.f;
        for (int j = 0; j < AKS; j++) sum += __ldg(&al2d[(a * AKS + k) * AKS + j]);
        sm.wal[tid] = sum;
    }
    // conv slab (halo 3; OOB/pad -> sentinel so iso == 0 exactly)
    for (int i = tid; i < RIN * POSP; i += 256) {
        int r = i / POSP, q = i - r * POSP;
        int gy = gy0 + r - 3, gx = gx0 + q - 3;
        sm.conv[i] = (q < 70 && gy >= 0 && gy < HH && gx >= 0 && gx < WW)
                     ? __ldg(&convmap[(size_t)gy * WW + gx]) : -1e30f;
    }
    float cn0 = __ldg(&centers[2 * p]);
    float cn1 = __ldg(&centers[2 * p + 1]);
    __syncthreads();

    float2 wk[AA][4];
#pragma unroll
    for (int a = 0; a < AA; a++)
#pragma unroll
        for (int k = 0; k < 4; k++) {
            float wv = sm.wal[a * 4 + k];
            wk[a][k] = make_float2(wv, wv);
        }

    const size_t ASTR = (size_t)BB * SS * CCH * HH * WW * (NB / 2);  // float2

    float invb = 1.f / __ldg(&betas[b]);
    float nrm = 0.3989422804014327f * invb;
    float kf2 = -0.5f * invb * invb * 1.44269504088896f;   // kf * log2(e)
    float lb = __log2f(nrm);

    float2 acc[2][7];     // alpha0/1 vertical scatter rings
    float2 d2[7];         // alpha2 hconv delay line (static rotation)
    float2* outb = (float2*)out +
                   (size_t)((b * SS + s) * CCH + c) * (HH * WW * (NB / 2));
    const int xoff = 8 * w + xi;

#pragma unroll 1
    for (int r7 = 0; r7 < 6; r7++) {
#pragma unroll
        for (int rr = 0; rr < 7; rr++) {
            int row = r7 * 7 + rr;
            if (row < RIN) {
                // ---- produce this warp's 16 iso positions (private slab) ----
                const float* crow = &sm.conv[row * POSP + xoff];
                float cva = crow[0];
                float cvb = crow[8];
                float da0 = cva - cn0, da1 = cva - cn1;
                float db0 = cvb - cn0, db1 = cvb - cn1;
                float2 e1, e2;
                e1.x = ex2f(fmaf(kf2, da0 * da0, lb));
                e1.y = ex2f(fmaf(kf2, da1 * da1, lb));
                e2.x = ex2f(fmaf(kf2, db0 * db0, lb));
                e2.y = ex2f(fmaf(kf2, db1 * db1, lb));
                float2* ps = sm.priv[row & 1][w];
                ps[xi * 4 + p] = e1;
                ps[(xi + 8) * 4 + p] = e2;
                __syncwarp();

                // ---- horizontal window (tap0 = own register) ----
                const float2* wp8 = &ps[xi * 4 + p];
                float2 t1 = wp8[4],  t2 = wp8[8],  t3 = wp8[12];
                float2 t4 = wp8[16], t5 = wp8[20], t6 = wp8[24];
                float2 s0 = fadd2(e1, t6);
                float2 s1 = fadd2(t1, t5);
                float2 s2 = fadd2(t2, t4);

                float2 hv0 = fmul2(wk[0][3], t3);
                float2 hv1 = fmul2(wk[1][3], t3);
                float2 hv2 = fmul2(wk[2][3], t3);
                hv0 = ffma2(wk[0][0], s0, hv0);
                hv1 = ffma2(wk[1][0], s0, hv1);
                hv2 = ffma2(wk[2][0], s0, hv2);
                hv0 = ffma2(wk[0][1], s1, hv0);
                hv1 = ffma2(wk[1][1], s1, hv1);
                hv2 = ffma2(wk[2][1], s1, hv2);
                hv0 = ffma2(wk[0][2], s2, hv0);
                hv1 = ffma2(wk[1][2], s2, hv1);
                hv2 = ffma2(wk[2][2], s2, hv2);

                // alpha2: register delay line (slot = row % 7 == rr)
                d2[rr] = hv2;

                // alphas 0,1: register scatter rings (stale slots are
                // re-initialized at t==0 before any store)
#pragma unroll
                for (int t = 0; t < 7; t++) {
                    const int slot = ((rr - t) % 7 + 7) % 7;
                    const int wi = (t < 4) ? t : 6 - t;
                    if (t == 0) {
                        acc[0][slot] = fmul2(wk[0][wi], hv0);
                        acc[1][slot] = fmul2(wk[1][wi], hv1);
                    } else {
                        acc[0][slot] = ffma2(wk[0][wi], hv0, acc[0][slot]);
                        acc[1][slot] = ffma2(wk[1][wi], hv1, acc[1][slot]);
                    }
                }

                // ---- completed output row y = row - 6 ----
                if (row >= 6) {
                    const int slot = (rr + 1) % 7;
                    // alpha2 vertical gather from the delay line:
                    // h[y+k] = d2[(rr+1+k)%7], h[y+6] = hv2
                    float2 sA = fadd2(d2[(rr + 1) % 7], hv2);
                    float2 sB = fadd2(d2[(rr + 2) % 7], d2[(rr + 6) % 7]);
                    float2 sC = fadd2(d2[(rr + 3) % 7], d2[(rr + 5) % 7]);
                    float2 o2 = fmul2(wk[2][3], d2[(rr + 4) % 7]);
                    o2 = ffma2(wk[2][0], sA, o2);
                    o2 = ffma2(wk[2][1], sB, o2);
                    o2 = ffma2(wk[2][2], sC, o2);

                    size_t off = ((size_t)(gy0 + row - 6) * WW + gx0 + xoff)
                                 * (NB / 2) + p;
                    outb[off] = acc[0][slot];
                    outb[off + ASTR] = acc[1][slot];
                    outb[off + 2 * ASTR] = o2;
                }
            }
        }
    }
}

// ---------------------------------------------------------------------------
extern "C" void kernel_launch(void* const* d_in, const int* in_sizes, int n_in,
                              void* d_out, int out_size) {
    const float* im      = (const float*)d_in[0];   // (512,512,3)
    const float* sig2d   = (const float*)d_in[1];   // (2,9,9)
    const float* al2d    = (const float*)d_in[2];   // (3,7,7)
    const float* centers = (const float*)d_in[3];   // (8,)
    const float* betas   = (const float*)d_in[4];   // (2,)
    float* out = (float*)d_out;

    dim3 gs(WW / STW, HH / STH, CCH);
    k_sigma<<<gs, 256>>>(im, sig2d);
    dim3 g(WW / W_T, HH / H_T, CCH * SS * BB);
    k_loi<<<g, 256>>>(al2d, centers, betas, out);
}

// round 15
// speedup vs baseline: 1.2784x; 1.2121x over previous
#include <cuda_runtime.h>
#include <cstdint>

#define HH 512
#define WW 512
#define CCH 3
#define SS 2
#define AA 3
#define NB 8
#define BB 2
#define SKS 9
#define AKS 7

__device__ float g_conv[CCH * SS * HH * WW];   // sigma-blurred maps

// ---------------------------------------------------------------------------
// Fused sigma blur: clip + separable 9-tap (both sigmas) per 32x32 tile.
// 1D weights (= row sums of the 2D kernel, exact rank-1) derived per CTA.
// ---------------------------------------------------------------------------
#define STW 32
#define STH 32
#define SIN 40

__global__ __launch_bounds__(256) void k_sigma(const float* __restrict__ im,
                                               const float* __restrict__ sig2d) {
    __shared__ float s_in[SIN][SIN];
    __shared__ float s_ht[SS][SIN][STW + 1];
    __shared__ float wsig[SS * 5];
    int tid = threadIdx.x;
    int c = blockIdx.z;
    int gy0 = blockIdx.y * STH, gx0 = blockIdx.x * STW;

    if (tid < SS * 5) {
        int s = tid / 5, k = tid % 5;
        float sum = 0.f;
        for (int j = 0; j < SKS; j++) sum += __ldg(&sig2d[(s * SKS + k) * SKS + j]);
        wsig[tid] = sum;
    }
    for (int i = tid; i < SIN * SIN; i += 256) {
        int r = i / SIN, q = i - r * SIN;
        int gy = gy0 + r - 4, gx = gx0 + q - 4;
        float v = 0.f;
        if (gy >= 0 && gy < HH && gx >= 0 && gx < WW) {
            v = __ldg(&im[((size_t)gy * WW + gx) * CCH + c]);
            v = fminf(fmaxf(v, 0.f), 1.f);
        }
        s_in[r][q] = v;
    }
    __syncthreads();
    float w[SS][5];
#pragma unroll
    for (int s = 0; s < SS; s++)
#pragma unroll
        for (int k = 0; k < 5; k++) w[s][k] = wsig[s * 5 + k];

    for (int i = tid; i < SIN * STW; i += 256) {
        int r = i / STW, x = i - r * STW;
        const float* row = &s_in[r][x];
        float p0 = row[0] + row[8], p1 = row[1] + row[7];
        float p2 = row[2] + row[6], p3 = row[3] + row[5];
        float m = row[4];
#pragma unroll
        for (int s = 0; s < SS; s++) {
            float acc = w[s][4] * m;
            acc = fmaf(w[s][0], p0, acc);
            acc = fmaf(w[s][1], p1, acc);
            acc = fmaf(w[s][2], p2, acc);
            acc = fmaf(w[s][3], p3, acc);
            s_ht[s][r][x] = acc;
        }
    }
    __syncthreads();

    for (int i = tid; i < STH * STW; i += 256) {
        int y = i / STW, x = i - y * STW;
#pragma unroll
        for (int s = 0; s < SS; s++) {
            const float* col = &s_ht[s][y][x];
            const int L = STW + 1;
            float p0 = col[0] + col[8 * L], p1 = col[1 * L] + col[7 * L];
            float p2 = col[2 * L] + col[6 * L], p3 = col[3 * L] + col[5 * L];
            float m = col[4 * L];
            float acc = w[s][4] * m;
            acc = fmaf(w[s][0], p0, acc);
            acc = fmaf(w[s][1], p1, acc);
            acc = fmaf(w[s][2], p2, acc);
            acc = fmaf(w[s][3], p3, acc);
            g_conv[(((size_t)c * SS + s) * HH + gy0 + y) * WW + gx0 + x] = acc;
        }
    }
}

// ---------------------------------------------------------------------------
// Packed f32x2 + ex2 helpers
// ---------------------------------------------------------------------------
union F2U { float2 f; unsigned long long u; };
__device__ __forceinline__ float2 ffma2(float2 a, float2 b, float2 c) {
    F2U A, B, C, D; A.f = a; B.f = b; C.f = c;
    asm("fma.rn.f32x2 %0, %1, %2, %3;" : "=l"(D.u) : "l"(A.u), "l"(B.u), "l"(C.u));
    return D.f;
}
__device__ __forceinline__ float2 fmul2(float2 a, float2 b) {
    F2U A, B, D; A.f = a; B.f = b;
    asm("mul.rn.f32x2 %0, %1, %2;" : "=l"(D.u) : "l"(A.u), "l"(B.u));
    return D.f;
}
__device__ __forceinline__ float2 fadd2(float2 a, float2 b) {
    F2U A, B, D; A.f = a; B.f = b;
    asm("add.rn.f32x2 %0, %1, %2;" : "=l"(D.u) : "l"(A.u), "l"(B.u));
    return D.f;
}
__device__ __forceinline__ float ex2f(float x) {
    float r; asm("ex2.approx.f32 %0, %1;" : "=f"(r) : "f"(x)); return r;
}

// ---------------------------------------------------------------------------
// K2: grid z = (c,s,b). Warp w owns x in [8w, 8w+8); lane l: p = l&3
// (binpair), xi = l>>2. TWO rows per iteration: produce both iso rows into a
// 4-slab warp-private ring, ONE __syncwarp, consume both. Vertical: register
// scatter rings (a0,a1) + 7-deep register delay line (a2), slot indices
// static via the 7-wide pair unroll. Output addressing via running offset.
// ---------------------------------------------------------------------------
#define W_T 64
#define H_T 32
#define RIN 38           // H_T + 6 input rows (= 19 pairs)
#define POSP 72          // padded conv row (lanes read up to 71; pad=sentinel)

struct SMemL {
    float  conv[RIN * POSP];       // 10944 B
    float2 priv[4][8][64];         // 16384 B, [slab][warp][pos*4+p]
    float  wal[AA * 4];
};

__global__ __launch_bounds__(256, 3) void k_loi(const float* __restrict__ al2d,
                                                const float* __restrict__ centers,
                                                const float* __restrict__ betas,
                                                float* __restrict__ out) {
    __shared__ SMemL sm;
    int tid = threadIdx.x;
    int l = tid & 31, w = tid >> 5;
    int p = l & 3, xi = l >> 2;
    int z = blockIdx.z;
    int b = z % BB;
    int cs = z / BB;
    int c = cs / SS, s = cs % SS;
    int gy0 = blockIdx.y * H_T;
    int gx0 = blockIdx.x * W_T;
    const float* convmap = g_conv + (size_t)cs * HH * WW;

    if (tid < AA * 4) {
        int a = tid >> 2, k = tid & 3;
        float sum = 0.f;
        for (int j = 0; j < AKS; j++) sum += __ldg(&al2d[(a * AKS + k) * AKS + j]);
        sm.wal[tid] = sum;
    }
    // conv slab (halo 3; OOB/pad -> sentinel so iso == 0 exactly)
    for (int i = tid; i < RIN * POSP; i += 256) {
        int r = i / POSP, q = i - r * POSP;
        int gy = gy0 + r - 3, gx = gx0 + q - 3;
        sm.conv[i] = (q < 70 && gy >= 0 && gy < HH && gx >= 0 && gx < WW)
                     ? __ldg(&convmap[(size_t)gy * WW + gx]) : -1e30f;
    }
    float cn0 = __ldg(&centers[2 * p]);
    float cn1 = __ldg(&centers[2 * p + 1]);
    __syncthreads();

    float2 wk[AA][4];
#pragma unroll
    for (int a = 0; a < AA; a++)
#pragma unroll
        for (int k = 0; k < 4; k++) {
            float wv = sm.wal[a * 4 + k];
            wk[a][k] = make_float2(wv, wv);
        }

    const size_t ASTR = (size_t)BB * SS * CCH * HH * WW * (NB / 2);  // float2

    float invb = 1.f / __ldg(&betas[b]);
    float nrm = 0.3989422804014327f * invb;
    float kf2 = -0.5f * invb * invb * 1.44269504088896f;   // kf * log2(e)
    float lb = __log2f(nrm);

    float2 acc[2][7];     // alpha0/1 vertical scatter rings
    float2 d2[7];         // alpha2 hconv delay line (static rotation)
    const int xoff = 8 * w + xi;
    float2* q0 = (float2*)out +
                 (size_t)((b * SS + s) * CCH + c) * (HH * WW * (NB / 2)) +
                 ((size_t)gy0 * WW + gx0 + xoff) * (NB / 2) + p;
    float2* q1 = q0 + ASTR;
    float2* q2 = q1 + ASTR;
    size_t yoff = 0;                      // advances 2 output rows per iter
    const float* cptr = sm.conv + xoff;   // row pair base

#pragma unroll 1
    for (int i7 = 0; i7 < 3; i7++) {
#pragma unroll
        for (int ii = 0; ii < 7; ii++) {
            int it = i7 * 7 + ii;
            if (it < 19) {
                const int slot0 = (2 * ii) % 7;       // (2*it)%7, static
                const int slot1 = (2 * ii + 1) % 7;
                int sb = (it & 1) << 1;
                float2* ps0 = sm.priv[sb][w];
                float2* ps1 = sm.priv[sb + 1][w];

                // ---- produce iso for rows r0=2it, r1=2it+1 ----
                float cva = cptr[0], cvb = cptr[8];
                float cvc = cptr[POSP], cvd = cptr[POSP + 8];
                cptr += 2 * POSP;
                float da0 = cva - cn0, da1 = cva - cn1;
                float db0 = cvb - cn0, db1 = cvb - cn1;
                float dc0 = cvc - cn0, dc1 = cvc - cn1;
                float dd0 = cvd - cn0, dd1 = cvd - cn1;
                float2 e1, e2, e3, e4;
                e1.x = ex2f(fmaf(kf2, da0 * da0, lb));
                e1.y = ex2f(fmaf(kf2, da1 * da1, lb));
                e2.x = ex2f(fmaf(kf2, db0 * db0, lb));
                e2.y = ex2f(fmaf(kf2, db1 * db1, lb));
                e3.x = ex2f(fmaf(kf2, dc0 * dc0, lb));
                e3.y = ex2f(fmaf(kf2, dc1 * dc1, lb));
                e4.x = ex2f(fmaf(kf2, dd0 * dd0, lb));
                e4.y = ex2f(fmaf(kf2, dd1 * dd1, lb));
                ps0[xi * 4 + p] = e1;
                ps0[(xi + 8) * 4 + p] = e2;
                ps1[xi * 4 + p] = e3;
                ps1[(xi + 8) * 4 + p] = e4;
                __syncwarp();

                // ================= row r0 =================
                {
                    const float2* wp8 = &ps0[xi * 4 + p];
                    float2 t1 = wp8[4],  t2 = wp8[8],  t3 = wp8[12];
                    float2 t4 = wp8[16], t5 = wp8[20], t6 = wp8[24];
                    float2 s0 = fadd2(e1, t6);
                    float2 s1 = fadd2(t1, t5);
                    float2 s2 = fadd2(t2, t4);
                    float2 hv0 = fmul2(wk[0][3], t3);
                    float2 hv1 = fmul2(wk[1][3], t3);
                    float2 hv2 = fmul2(wk[2][3], t3);
                    hv0 = ffma2(wk[0][0], s0, hv0);
                    hv1 = ffma2(wk[1][0], s0, hv1);
                    hv2 = ffma2(wk[2][0], s0, hv2);
                    hv0 = ffma2(wk[0][1], s1, hv0);
                    hv1 = ffma2(wk[1][1], s1, hv1);
                    hv2 = ffma2(wk[2][1], s1, hv2);
                    hv0 = ffma2(wk[0][2], s2, hv0);
                    hv1 = ffma2(wk[1][2], s2, hv1);
                    hv2 = ffma2(wk[2][2], s2, hv2);

                    d2[slot0] = hv2;
#pragma unroll
                    for (int t = 0; t < 7; t++) {
                        const int slot = ((slot0 - t) % 7 + 7) % 7;
                        const int wi = (t < 4) ? t : 6 - t;
                        if (t == 0) {
                            acc[0][slot] = fmul2(wk[0][wi], hv0);
                            acc[1][slot] = fmul2(wk[1][wi], hv1);
                        } else {
                            acc[0][slot] = ffma2(wk[0][wi], hv0, acc[0][slot]);
                            acc[1][slot] = ffma2(wk[1][wi], hv1, acc[1][slot]);
                        }
                    }
                    if (it >= 3) {            // output y = 2*it - 6
                        float2 sA = fadd2(d2[(slot0 + 1) % 7], hv2);
                        float2 sB = fadd2(d2[(slot0 + 2) % 7], d2[(slot0 + 6) % 7]);
                        float2 sC = fadd2(d2[(slot0 + 3) % 7], d2[(slot0 + 5) % 7]);
                        float2 o2 = fmul2(wk[2][3], d2[(slot0 + 4) % 7]);
                        o2 = ffma2(wk[2][0], sA, o2);
                        o2 = ffma2(wk[2][1], sB, o2);
                        o2 = ffma2(wk[2][2], sC, o2);
                        q0[yoff] = acc[0][(slot0 + 1) % 7];
                        q1[yoff] = acc[1][(slot0 + 1) % 7];
                        q2[yoff] = o2;
                    }
                }
                // ================= row r1 =================
                {
                    const float2* wp8 = &ps1[xi * 4 + p];
                    float2 t1 = wp8[4],  t2 = wp8[8],  t3 = wp8[12];
                    float2 t4 = wp8[16], t5 = wp8[20], t6 = wp8[24];
                    float2 s0 = fadd2(e3, t6);
                    float2 s1 = fadd2(t1, t5);
                    float2 s2 = fadd2(t2, t4);
                    float2 hv0 = fmul2(wk[0][3], t3);
                    float2 hv1 = fmul2(wk[1][3], t3);
                    float2 hv2 = fmul2(wk[2][3], t3);
                    hv0 = ffma2(wk[0][0], s0, hv0);
                    hv1 = ffma2(wk[1][0], s0, hv1);
                    hv2 = ffma2(wk[2][0], s0, hv2);
                    hv0 = ffma2(wk[0][1], s1, hv0);
                    hv1 = ffma2(wk[1][1], s1, hv1);
                    hv2 = ffma2(wk[2][1], s1, hv2);
                    hv0 = ffma2(wk[0][2], s2, hv0);
                    hv1 = ffma2(wk[1][2], s2, hv1);
                    hv2 = ffma2(wk[2][2], s2, hv2);

#pragma unroll
                    for (int t = 0; t < 7; t++) {
                        const int slot = ((slot1 - t) % 7 + 7) % 7;
                        const int wi = (t < 4) ? t : 6 - t;
                        if (t == 0) {
                            acc[0][slot] = fmul2(wk[0][wi], hv0);
                            acc[1][slot] = fmul2(wk[1][wi], hv1);
                        } else {
                            acc[0][slot] = ffma2(wk[0][wi], hv0, acc[0][slot]);
                            acc[1][slot] = ffma2(wk[1][wi], hv1, acc[1][slot]);
                        }
                    }
                    d2[slot1] = hv2;         // after r0's gather read old value
                    if (it >= 3) {            // output y = 2*it - 5
                        float2 sA = fadd2(d2[(slot1 + 1) % 7], hv2);
                        float2 sB = fadd2(d2[(slot1 + 2) % 7], d2[(slot1 + 6) % 7]);
                        float2 sC = fadd2(d2[(slot1 + 3) % 7], d2[(slot1 + 5) % 7]);
                        float2 o2 = fmul2(wk[2][3], d2[(slot1 + 4) % 7]);
                        o2 = ffma2(wk[2][0], sA, o2);
                        o2 = ffma2(wk[2][1], sB, o2);
                        o2 = ffma2(wk[2][2], sC, o2);
                        size_t yo = yoff + (size_t)WW * (NB / 2);
                        q0[yo] = acc[0][(slot1 + 1) % 7];
                        q1[yo] = acc[1][(slot1 + 1) % 7];
                        q2[yo] = o2;
                        yoff += (size_t)2 * WW * (NB / 2);
                    }
                }
            }
        }
    }
}

// ---------------------------------------------------------------------------
extern "C" void kernel_launch(void* const* d_in, const int* in_sizes, int n_in,
                              void* d_out, int out_size) {
    const float* im      = (const float*)d_in[0];   // (512,512,3)
    const float* sig2d   = (const float*)d_in[1];   // (2,9,9)
    const float* al2d    = (const float*)d_in[2];   // (3,7,7)
    const float* centers = (const float*)d_in[3];   // (8,)
    const float* betas   = (const float*)d_in[4];   // (2,)
    float* out = (float*)d_out;

    dim3 gs(WW / STW, HH / STH, CCH);
    k_sigma<<<gs, 256>>>(im, sig2d);
    dim3 g(WW / W_T, HH / H_T, CCH * SS * BB);
    k_loi<<<g, 256>>>(al2d, centers, betas, out);
}

// round 17
// speedup vs baseline: 1.3324x; 1.0422x over previous
#include <cuda_runtime.h>
#include <cstdint>

#define HH 512
#define WW 512
#define CCH 3
#define SS 2
#define AA 3
#define NB 8
#define BB 2
#define SKS 9
#define AKS 7

__device__ float g_conv[CCH * SS * HH * WW];   // sigma-blurred maps

// ---------------------------------------------------------------------------
// Fused sigma blur: clip + separable 9-tap (both sigmas) per 32x32 tile.
// 1D weights (= row sums of the 2D kernel, exact rank-1) derived per CTA.
// ---------------------------------------------------------------------------
#define STW 32
#define STH 32
#define SIN 40

__global__ __launch_bounds__(256) void k_sigma(const float* __restrict__ im,
                                               const float* __restrict__ sig2d) {
    __shared__ float s_in[SIN][SIN];
    __shared__ float s_ht[SS][SIN][STW + 1];
    __shared__ float wsig[SS * 5];
    int tid = threadIdx.x;
    int c = blockIdx.z;
    int gy0 = blockIdx.y * STH, gx0 = blockIdx.x * STW;

    if (tid < SS * 5) {
        int s = tid / 5, k = tid % 5;
        float sum = 0.f;
        for (int j = 0; j < SKS; j++) sum += __ldg(&sig2d[(s * SKS + k) * SKS + j]);
        wsig[tid] = sum;
    }
    for (int i = tid; i < SIN * SIN; i += 256) {
        int r = i / SIN, q = i - r * SIN;
        int gy = gy0 + r - 4, gx = gx0 + q - 4;
        float v = 0.f;
        if (gy >= 0 && gy < HH && gx >= 0 && gx < WW) {
            v = __ldg(&im[((size_t)gy * WW + gx) * CCH + c]);
            v = fminf(fmaxf(v, 0.f), 1.f);
        }
        s_in[r][q] = v;
    }
    __syncthreads();
    float w[SS][5];
#pragma unroll
    for (int s = 0; s < SS; s++)
#pragma unroll
        for (int k = 0; k < 5; k++) w[s][k] = wsig[s * 5 + k];

    for (int i = tid; i < SIN * STW; i += 256) {
        int r = i / STW, x = i - r * STW;
        const float* row = &s_in[r][x];
        float p0 = row[0] + row[8], p1 = row[1] + row[7];
        float p2 = row[2] + row[6], p3 = row[3] + row[5];
        float m = row[4];
#pragma unroll
        for (int s = 0; s < SS; s++) {
            float acc = w[s][4] * m;
            acc = fmaf(w[s][0], p0, acc);
            acc = fmaf(w[s][1], p1, acc);
            acc = fmaf(w[s][2], p2, acc);
            acc = fmaf(w[s][3], p3, acc);
            s_ht[s][r][x] = acc;
        }
    }
    __syncthreads();

    for (int i = tid; i < STH * STW; i += 256) {
        int y = i / STW, x = i - y * STW;
#pragma unroll
        for (int s = 0; s < SS; s++) {
            const float* col = &s_ht[s][y][x];
            const int L = STW + 1;
            float p0 = col[0] + col[8 * L], p1 = col[1 * L] + col[7 * L];
            float p2 = col[2 * L] + col[6 * L], p3 = col[3 * L] + col[5 * L];
            float m = col[4 * L];
            float acc = w[s][4] * m;
            acc = fmaf(w[s][0], p0, acc);
            acc = fmaf(w[s][1], p1, acc);
            acc = fmaf(w[s][2], p2, acc);
            acc = fmaf(w[s][3], p3, acc);
            g_conv[(((size_t)c * SS + s) * HH + gy0 + y) * WW + gx0 + x] = acc;
        }
    }
}

// ---------------------------------------------------------------------------
// Packed f32x2 + ex2 helpers
// ---------------------------------------------------------------------------
union F2U { float2 f; unsigned long long u; };
__device__ __forceinline__ float2 ffma2(float2 a, float2 b, float2 c) {
    F2U A, B, C, D; A.f = a; B.f = b; C.f = c;
    asm("fma.rn.f32x2 %0, %1, %2, %3;" : "=l"(D.u) : "l"(A.u), "l"(B.u), "l"(C.u));
    return D.f;
}
__device__ __forceinline__ float2 fmul2(float2 a, float2 b) {
    F2U A, B, D; A.f = a; B.f = b;
    asm("mul.rn.f32x2 %0, %1, %2;" : "=l"(D.u) : "l"(A.u), "l"(B.u));
    return D.f;
}
__device__ __forceinline__ float2 fadd2(float2 a, float2 b) {
    F2U A, B, D; A.f = a; B.f = b;
    asm("add.rn.f32x2 %0, %1, %2;" : "=l"(D.u) : "l"(A.u), "l"(B.u));
    return D.f;
}
__device__ __forceinline__ float ex2f(float x) {
    float r; asm("ex2.approx.f32 %0, %1;" : "=f"(r) : "f"(x)); return r;
}

// ---------------------------------------------------------------------------
// K2: 128-thread CTAs (4 warps), grid z = (c,s,b). Warp w owns x in
// [8w, 8w+8); lane l: p = l&3 (binpair), xi = l>>2. Two rows per iteration
// into a 4-slab warp-private ring, ONE __syncwarp, consume both. Vertical:
// 7-deep register DELAY LINES for ALL THREE alphas (symmetric gather at
// output time; slot indices static via the 7-wide pair unroll). iso via
// polynomial ex2: nrm*exp(kf d^2) = ex2(kf2 cv^2 + B cv + C).
// ---------------------------------------------------------------------------
#define W_T 32
#define H_T 32
#define RIN 38           // H_T + 6 input rows (= 19 pairs)
#define POSP 40          // padded conv row (needs 38; lanes read up to 39)
#define NW 4

struct SMemL {
    float  conv[RIN * POSP];       // 6080 B
    float2 priv[4][NW][64];        // 8192 B, [slab][warp][pos*4+p]
    float  wal[AA * 4];
};

__global__ __launch_bounds__(128, 6) void k_loi(const float* __restrict__ al2d,
                                                const float* __restrict__ centers,
                                                const float* __restrict__ betas,
                                                float* __restrict__ out) {
    __shared__ SMemL sm;
    int tid = threadIdx.x;
    int l = tid & 31, w = tid >> 5;
    int p = l & 3, xi = l >> 2;
    int z = blockIdx.z;
    int b = z % BB;
    int cs = z / BB;
    int c = cs / SS, s = cs % SS;
    int gy0 = blockIdx.y * H_T;
    int gx0 = blockIdx.x * W_T;
    const float* convmap = g_conv + (size_t)cs * HH * WW;

    if (tid < AA * 4) {
        int a = tid >> 2, k = tid & 3;
        float sum = 0.f;
        for (int j = 0; j < AKS; j++) sum += __ldg(&al2d[(a * AKS + k) * AKS + j]);
        sm.wal[tid] = sum;
    }
    // conv slab (halo 3; OOB/pad -> sentinel so iso == 0 exactly)
    for (int i = tid; i < RIN * POSP; i += 128) {
        int r = i / POSP, q = i - r * POSP;
        int gy = gy0 + r - 3, gx = gx0 + q - 3;
        sm.conv[i] = (q < 38 && gy >= 0 && gy < HH && gx >= 0 && gx < WW)
                     ? __ldg(&convmap[(size_t)gy * WW + gx]) : -1e30f;
    }
    float cn0 = __ldg(&centers[2 * p]);
    float cn1 = __ldg(&centers[2 * p + 1]);
    __syncthreads();

    float2 wk[AA][4];
#pragma unroll
    for (int a = 0; a < AA; a++)
#pragma unroll
        for (int k = 0; k < 4; k++) {
            float wv = sm.wal[a * 4 + k];
            wk[a][k] = make_float2(wv, wv);
        }

    const size_t ASTR = (size_t)BB * SS * CCH * HH * WW * (NB / 2);  // float2

    float invb = 1.f / __ldg(&betas[b]);
    float nrm = 0.3989422804014327f * invb;
    float kf2 = -0.5f * invb * invb * 1.44269504088896f;   // kf * log2(e)
    float lb = __log2f(nrm);
    // per-bin polynomial: arg(cv) = kf2*cv^2 + Bq*cv + Cq
    float B0 = -2.f * kf2 * cn0, C0 = fmaf(kf2, cn0 * cn0, lb);
    float B1 = -2.f * kf2 * cn1, C1 = fmaf(kf2, cn1 * cn1, lb);

    float2 dl[AA][7];     // per-alpha hconv delay lines (static rotation)
    const int xoff = 8 * w + xi;
    float2* q0 = (float2*)out +
                 (size_t)((b * SS + s) * CCH + c) * (HH * WW * (NB / 2)) +
                 ((size_t)gy0 * WW + gx0 + xoff) * (NB / 2) + p;
    float2* q1 = q0 + ASTR;
    float2* q2 = q1 + ASTR;
    size_t yoff = 0;                      // advances 2 output rows per iter
    const float* cptr = sm.conv + xoff;   // row pair base

#pragma unroll 1
    for (int i7 = 0; i7 < 3; i7++) {
#pragma unroll
        for (int ii = 0; ii < 7; ii++) {
            int it = i7 * 7 + ii;
            if (it < 19) {
                const int slot0 = (2 * ii) % 7;       // (2*it)%7, static
                const int slot1 = (2 * ii + 1) % 7;
                int sb = (it & 1) << 1;
                float2* ps0 = sm.priv[sb][w];
                float2* ps1 = sm.priv[sb + 1][w];

                // ---- produce iso for rows r0=2it, r1=2it+1 ----
                float cva = cptr[0], cvb = cptr[8];
                float cvc = cptr[POSP], cvd = cptr[POSP + 8];
                cptr += 2 * POSP;
                float qa = cva * cva, qb = cvb * cvb;
                float qc = cvc * cvc, qd = cvd * cvd;
                float2 e1, e2, e3, e4;
                e1.x = ex2f(fmaf(kf2, qa, fmaf(B0, cva, C0)));
                e1.y = ex2f(fmaf(kf2, qa, fmaf(B1, cva, C1)));
                e2.x = ex2f(fmaf(kf2, qb, fmaf(B0, cvb, C0)));
                e2.y = ex2f(fmaf(kf2, qb, fmaf(B1, cvb, C1)));
                e3.x = ex2f(fmaf(kf2, qc, fmaf(B0, cvc, C0)));
                e3.y = ex2f(fmaf(kf2, qc, fmaf(B1, cvc, C1)));
                e4.x = ex2f(fmaf(kf2, qd, fmaf(B0, cvd, C0)));
                e4.y = ex2f(fmaf(kf2, qd, fmaf(B1, cvd, C1)));
                ps0[xi * 4 + p] = e1;
                ps0[(xi + 8) * 4 + p] = e2;
                ps1[xi * 4 + p] = e3;
                ps1[(xi + 8) * 4 + p] = e4;
                __syncwarp();

                // ================= row r0 =================
                {
                    const float2* wp8 = &ps0[xi * 4 + p];
                    float2 t1 = wp8[4],  t2 = wp8[8],  t3 = wp8[12];
                    float2 t4 = wp8[16], t5 = wp8[20], t6 = wp8[24];
                    float2 s0 = fadd2(e1, t6);
                    float2 s1 = fadd2(t1, t5);
                    float2 s2 = fadd2(t2, t4);
                    float2 hv0 = fmul2(wk[0][3], t3);
                    float2 hv1 = fmul2(wk[1][3], t3);
                    float2 hv2 = fmul2(wk[2][3], t3);
                    hv0 = ffma2(wk[0][0], s0, hv0);
                    hv1 = ffma2(wk[1][0], s0, hv1);
                    hv2 = ffma2(wk[2][0], s0, hv2);
                    hv0 = ffma2(wk[0][1], s1, hv0);
                    hv1 = ffma2(wk[1][1], s1, hv1);
                    hv2 = ffma2(wk[2][1], s1, hv2);
                    hv0 = ffma2(wk[0][2], s2, hv0);
                    hv1 = ffma2(wk[1][2], s2, hv1);
                    hv2 = ffma2(wk[2][2], s2, hv2);

                    if (it >= 3) {            // output y = 2*it - 6
                        float2 r0v, r1v, r2v;
                        {
                            float2 sA = fadd2(dl[0][(slot0 + 1) % 7], hv0);
                            float2 sB = fadd2(dl[0][(slot0 + 2) % 7], dl[0][(slot0 + 6) % 7]);
                            float2 sC = fadd2(dl[0][(slot0 + 3) % 7], dl[0][(slot0 + 5) % 7]);
                            float2 o = fmul2(wk[0][3], dl[0][(slot0 + 4) % 7]);
                            o = ffma2(wk[0][0], sA, o);
                            o = ffma2(wk[0][1], sB, o);
                            r0v = ffma2(wk[0][2], sC, o);
                        }
                        {
                            float2 sA = fadd2(dl[1][(slot0 + 1) % 7], hv1);
                            float2 sB = fadd2(dl[1][(slot0 + 2) % 7], dl[1][(slot0 + 6) % 7]);
                            float2 sC = fadd2(dl[1][(slot0 + 3) % 7], dl[1][(slot0 + 5) % 7]);
                            float2 o = fmul2(wk[1][3], dl[1][(slot0 + 4) % 7]);
                            o = ffma2(wk[1][0], sA, o);
                            o = ffma2(wk[1][1], sB, o);
                            r1v = ffma2(wk[1][2], sC, o);
                        }
                        {
                            float2 sA = fadd2(dl[2][(slot0 + 1) % 7], hv2);
                            float2 sB = fadd2(dl[2][(slot0 + 2) % 7], dl[2][(slot0 + 6) % 7]);
                            float2 sC = fadd2(dl[2][(slot0 + 3) % 7], dl[2][(slot0 + 5) % 7]);
                            float2 o = fmul2(wk[2][3], dl[2][(slot0 + 4) % 7]);
                            o = ffma2(wk[2][0], sA, o);
                            o = ffma2(wk[2][1], sB, o);
                            r2v = ffma2(wk[2][2], sC, o);
                        }
                        q0[yoff] = r0v;
                        q1[yoff] = r1v;
                        q2[yoff] = r2v;
                    }
                    dl[0][slot0] = hv0;
                    dl[1][slot0] = hv1;
                    dl[2][slot0] = hv2;
                }
                // ================= row r1 =================
                {
                    const float2* wp8 = &ps1[xi * 4 + p];
                    float2 t1 = wp8[4],  t2 = wp8[8],  t3 = wp8[12];
                    float2 t4 = wp8[16], t5 = wp8[20], t6 = wp8[24];
                    float2 s0 = fadd2(e3, t6);
                    float2 s1 = fadd2(t1, t5);
                    float2 s2 = fadd2(t2, t4);
                    float2 hv0 = fmul2(wk[0][3], t3);
                    float2 hv1 = fmul2(wk[1][3], t3);
                    float2 hv2 = fmul2(wk[2][3], t3);
                    hv0 = ffma2(wk[0][0], s0, hv0);
                    hv1 = ffma2(wk[1][0], s0, hv1);
                    hv2 = ffma2(wk[2][0], s0, hv2);
                    hv0 = ffma2(wk[0][1], s1, hv0);
                    hv1 = ffma2(wk[1][1], s1, hv1);
                    hv2 = ffma2(wk[2][1], s1, hv2);
                    hv0 = ffma2(wk[0][2], s2, hv0);
                    hv1 = ffma2(wk[1][2], s2, hv1);
                    hv2 = ffma2(wk[2][2], s2, hv2);

                    if (it >= 3) {            // output y = 2*it - 5
                        float2 r0v, r1v, r2v;
                        {
                            float2 sA = fadd2(dl[0][(slot1 + 1) % 7], hv0);
                            float2 sB = fadd2(dl[0][(slot1 + 2) % 7], dl[0][(slot1 + 6) % 7]);
                            float2 sC = fadd2(dl[0][(slot1 + 3) % 7], dl[0][(slot1 + 5) % 7]);
                            float2 o = fmul2(wk[0][3], dl[0][(slot1 + 4) % 7]);
                            o = ffma2(wk[0][0], sA, o);
                            o = ffma2(wk[0][1], sB, o);
                            r0v = ffma2(wk[0][2], sC, o);
                        }
                        {
                            float2 sA = fadd2(dl[1][(slot1 + 1) % 7], hv1);
                            float2 sB = fadd2(dl[1][(slot1 + 2) % 7], dl[1][(slot1 + 6) % 7]);
                            float2 sC = fadd2(dl[1][(slot1 + 3) % 7], dl[1][(slot1 + 5) % 7]);
                            float2 o = fmul2(wk[1][3], dl[1][(slot1 + 4) % 7]);
                            o = ffma2(wk[1][0], sA, o);
                            o = ffma2(wk[1][1], sB, o);
                            r1v = ffma2(wk[1][2], sC, o);
                        }
                        {
                            float2 sA = fadd2(dl[2][(slot1 + 1) % 7], hv2);
                            float2 sB = fadd2(dl[2][(slot1 + 2) % 7], dl[2][(slot1 + 6) % 7]);
                            float2 sC = fadd2(dl[2][(slot1 + 3) % 7], dl[2][(slot1 + 5) % 7]);
                            float2 o = fmul2(wk[2][3], dl[2][(slot1 + 4) % 7]);
                            o = ffma2(wk[2][0], sA, o);
                            o = ffma2(wk[2][1], sB, o);
                            r2v = ffma2(wk[2][2], sC, o);
                        }
                        size_t yo = yoff + (size_t)WW * (NB / 2);
                        q0[yo] = r0v;
                        q1[yo] = r1v;
                        q2[yo] = r2v;
                        yoff += (size_t)2 * WW * (NB / 2);
                    }
                    dl[0][slot1] = hv0;
                    dl[1][slot1] = hv1;
                    dl[2][slot1] = hv2;
                }
            }
        }
    }
}

// ---------------------------------------------------------------------------
extern "C" void kernel_launch(void* const* d_in, const int* in_sizes, int n_in,
                              void* d_out, int out_size) {
    const float* im      = (const float*)d_in[0];   // (512,512,3)
    const float* sig2d   = (const float*)d_in[1];   // (2,9,9)
    const float* al2d    = (const float*)d_in[2];   // (3,7,7)
    const float* centers = (const float*)d_in[3];   // (8,)
    const float* betas   = (const float*)d_in[4];   // (2,)
    float* out = (float*)d_out;

    dim3 gs(WW / STW, HH / STH, CCH);
    k_sigma<<<gs, 256>>>(im, sig2d);
    dim3 g(WW / W_T, HH / H_T, CCH * SS * BB);
    k_loi<<<g, 128>>>(al2d, centers, betas, out);
}